// round 16
// baseline (speedup 1.0000x reference)
#include <cuda_runtime.h>
#include <cuda_fp16.h>
#include <stdint.h>
#include <math.h>

#define FEAT     256
#define MAX_DEG  128
#define BATCH    1024
#define NS0      10
#define NS1      25
#define M1SZ     (BATCH * NS0)     /* 10240 */
#define MEXT     (M1SZ + BATCH)    /* 11264 */
#define BM       128               /* gemm1 M-tile */
#define HOP1_BLKS (M1SZ / 4)       /* 2560 */
#define WT_BLKS   128
#define HOP0_BLKS (BATCH / 4)      /* 256 */
#define WMAT     (128 * FEAT)      /* halves per K-major weight matrix */
#define WMATU    (WMAT / 2)        /* u32 per matrix = 16384 */
#define LROWS    16

// ---------------- scratch (fp16) ----------------
__device__ __align__(16) __half g_H1h[MEXT * FEAT];
__device__ __align__(16) __half g_M1h[MEXT * FEAT];
__device__ __align__(16) __half g_C1h[MEXT * FEAT];   // rows M1SZ.. are C0
__device__ __align__(16) __half g_WTh[4 * WMAT];

// ---------------- threefry2x32 ----------------
__host__ __device__ __forceinline__ uint32_t rotl32_(uint32_t x, int r) {
    return (x << r) | (x >> (32 - r));
}
__host__ __device__ inline void tf2x32(uint32_t k0, uint32_t k1,
                                       uint32_t x0, uint32_t x1,
                                       uint32_t &o0, uint32_t &o1) {
    uint32_t ks2 = k0 ^ k1 ^ 0x1BD11BDAu;
    x0 += k0; x1 += k1;
#define TFR(r) { x0 += x1; x1 = rotl32_(x1, (r)); x1 ^= x0; }
    TFR(13) TFR(15) TFR(26) TFR(6)
    x0 += k1;  x1 += ks2 + 1u;
    TFR(17) TFR(29) TFR(16) TFR(24)
    x0 += ks2; x1 += k0 + 2u;
    TFR(13) TFR(15) TFR(26) TFR(6)
    x0 += k0;  x1 += k1 + 3u;
    TFR(17) TFR(29) TFR(16) TFR(24)
    x0 += k1;  x1 += ks2 + 4u;
    TFR(13) TFR(15) TFR(26) TFR(6)
    x0 += ks2; x1 += k0 + 5u;
#undef TFR
    o0 = x0; o1 = x1;
}
__device__ __forceinline__ int rnd_col(uint32_t k0, uint32_t k1, uint32_t t) {
    uint32_t a, b;
    tf2x32(k0, k1, 0u, t, a, b);
    return (int)((a ^ b) & (uint32_t)(MAX_DEG - 1));
}

// ---------------- helpers ----------------
__device__ __forceinline__ void mma_f16(float c[4], const uint32_t a[4],
                                        const uint32_t b[2]) {
    asm volatile(
        "mma.sync.aligned.m16n8k16.row.col.f32.f16.f16.f32 "
        "{%0,%1,%2,%3}, {%4,%5,%6,%7}, {%8,%9}, {%0,%1,%2,%3};"
        : "+f"(c[0]), "+f"(c[1]), "+f"(c[2]), "+f"(c[3])
        : "r"(a[0]), "r"(a[1]), "r"(a[2]), "r"(a[3]), "r"(b[0]), "r"(b[1]));
}
__device__ __forceinline__ void ldsm4(uint32_t r[4], uint32_t addr) {
    asm volatile(
        "ldmatrix.sync.aligned.m8n8.x4.shared.b16 {%0,%1,%2,%3}, [%4];"
        : "=r"(r[0]), "=r"(r[1]), "=r"(r[2]), "=r"(r[3]) : "r"(addr));
}
__device__ __forceinline__ uint32_t smem_u32(const void* p) {
    return (uint32_t)__cvta_generic_to_shared(p);
}
__device__ __forceinline__ void cp16(uint32_t s, const void* g) {
    asm volatile("cp.async.cg.shared.global [%0], [%1], 16;" :: "r"(s), "l"(g));
}
#define CP_COMMIT() asm volatile("cp.async.commit_group;" ::: "memory")
#define CP_WAIT1()  asm volatile("cp.async.wait_group 1;" ::: "memory")
#define CP_WAIT0()  asm volatile("cp.async.wait_group 0;" ::: "memory")
#define GDC_WAIT()  asm volatile("griddepcontrol.wait;" ::: "memory")
#define GDC_LAUNCH() asm volatile("griddepcontrol.launch_dependents;" ::: "memory")

__device__ __forceinline__ void st_half4(void* dst, float4 v) {
    __half2 a = __floats2half2_rn(v.x, v.y);
    __half2 b = __floats2half2_rn(v.z, v.w);
    uint2 u;
    u.x = *(uint32_t*)&a;
    u.y = *(uint32_t*)&b;
    *(uint2*)dst = u;
}

// ---------------- prep: hop1 + weight transposes + hop0 (proven R12) ------
__global__ void __launch_bounds__(256)
k_prep(const float4* __restrict__ feat4, const int* __restrict__ adj,
       const int* __restrict__ node_ids,
       const float* __restrict__ w0, const float* __restrict__ w1,
       const float* __restrict__ w2, const float* __restrict__ w3,
       uint32_t l0a, uint32_t l0b, uint32_t l1a, uint32_t l1b) {
    const int tid = threadIdx.x;
    uint2* H1u = (uint2*)g_H1h;
    uint2* M1u = (uint2*)g_M1h;

    if (blockIdx.x >= HOP1_BLKS + WT_BLKS) {
        __shared__ int s1g[40];
        const int i0 = (blockIdx.x - HOP1_BLKS - WT_BLKS) * 4;
        if (tid < 40) {
            const int j = i0 * NS0 + tid;
            int c0 = rnd_col(l0a, l0b, (uint32_t)j);
            s1g[tid] = adj[node_ids[j / NS0] * MAX_DEG + c0];
        }
        __syncthreads();
        const int lj = tid >> 6, c = tid & 63;
        const int i = i0 + lj;
        st_half4(&H1u[(size_t)(M1SZ + i) * 64 + c],
                 feat4[(size_t)node_ids[i] * 64 + c]);
        float ax = 0.f, ay = 0.f, az = 0.f, aw = 0.f;
#pragma unroll
        for (int s = 0; s < NS0; s++) {
            float4 v = feat4[(size_t)s1g[lj * NS0 + s] * 64 + c];
            ax += v.x; ay += v.y; az += v.z; aw += v.w;
        }
        const float inv = 1.0f / NS0;
        st_half4(&M1u[(size_t)(M1SZ + i) * 64 + c],
                 make_float4(ax * inv, ay * inv, az * inv, aw * inv));
        GDC_LAUNCH();
        return;
    }
    if (blockIdx.x >= HOP1_BLKS) {
        __shared__ float tile[32][33];
        const int wb = blockIdx.x - HOP1_BLKS;
        const int mat = wb >> 5;
        const int sub = wb & 31;
        const float* W = (mat == 0) ? w0 : (mat == 1) ? w1 : (mat == 2) ? w2 : w3;
        __half* WT = g_WTh + mat * WMAT;
        const int k0 = (sub >> 2) * 32;
        const int n0 = (sub & 3) * 32;
        const int c = tid & 31, rw = tid >> 5;
#pragma unroll
        for (int r = rw; r < 32; r += 8)
            tile[r][c] = W[(k0 + r) * 128 + n0 + c];
        __syncthreads();
#pragma unroll
        for (int r = rw; r < 32; r += 8)
            WT[(n0 + r) * FEAT + k0 + c] = __float2half_rn(tile[c][r]);
        GDC_LAUNCH();
        return;
    }
    const int j0 = blockIdx.x * 4;
    __shared__ int s1sh[4];
    __shared__ int s2s[4][NS1];
    if (tid < 4) {
        int j = j0 + tid;
        int c0 = rnd_col(l0a, l0b, (uint32_t)j);
        s1sh[tid] = adj[node_ids[j / NS0] * MAX_DEG + c0];
    }
    __syncthreads();
    if (tid < 4 * NS1) {
        int lj = tid / NS1, s = tid - lj * NS1;
        int c1 = rnd_col(l1a, l1b, (uint32_t)((j0 + lj) * NS1 + s));
        s2s[lj][s] = adj[s1sh[lj] * MAX_DEG + c1];
    }
    __syncthreads();
    const int lj = tid >> 6, c = tid & 63;
    const int j = j0 + lj;
    st_half4(&H1u[(size_t)j * 64 + c], feat4[(size_t)s1sh[lj] * 64 + c]);
    float ax = 0.f, ay = 0.f, az = 0.f, aw = 0.f;
#pragma unroll
    for (int s = 0; s < NS1; s++) {
        float4 v = feat4[(size_t)s2s[lj][s] * 64 + c];
        ax += v.x; ay += v.y; az += v.z; aw += v.w;
    }
    const float inv = 1.0f / NS1;
    st_half4(&M1u[(size_t)j * 64 + c],
             make_float4(ax * inv, ay * inv, az * inv, aw * inv));
    GDC_LAUNCH();
}

// ---------------- gemm1: fp16 mma, BM=128, A cp.async, B direct-LDG ------
// smem: A only, double-buffered: 2 x 128 x 36 u32.
#define SA1(b, r, c) smu[(b) * 4608 + (r) * 36 + (c)]
#define G1_SMEM (2 * 4608 * 4)

__global__ void __launch_bounds__(256)
k_gemm1() {
    extern __shared__ uint32_t smu[];
    const int tid = threadIdx.x, lane = tid & 31, wid = tid >> 5;
    const int wr = wid & 1, wc = wid >> 1;
    const int m0 = blockIdx.x * BM;
    const int arow8 = (lane & 7) + ((lane >> 3) & 1) * 8;
    const int akoff = ((lane >> 4) & 1) * 4;

    GDC_WAIT();

    const float4* __restrict__ A4 =
        (const float4*)(blockIdx.y ? g_M1h : g_H1h);
    const uint32_t* __restrict__ Bg =
        (const uint32_t*)g_WTh + (size_t)blockIdx.y * WMATU;
    const int colOff = blockIdx.y * 128;

    float acc[4][4][4];
#pragma unroll
    for (int mt = 0; mt < 4; mt++)
#pragma unroll
        for (int nt = 0; nt < 4; nt++)
#pragma unroll
            for (int q = 0; q < 4; q++) acc[mt][nt][q] = 0.f;

    auto stage = [&](int cc, int b) {
#pragma unroll
        for (int u = 0; u < 4; u++) {           // A: 1024 float4
            int fid = u * 256 + tid;
            int row = fid >> 3, q = fid & 7;
            cp16(smem_u32(&SA1(b, row, q * 4)),
                 &A4[(size_t)(m0 + row) * 32 + cc * 8 + q]);
        }
        CP_COMMIT();
    };

    // per-warp B base offsets (u32 index into Bg)
    const int bn = wc * 32 + (lane >> 2);       // n row for nt=0
    const int bk = (lane & 3);                  // k u32 offset within group

    stage(0, 0);
    for (int cc = 0; cc < 4; cc++) {
        if (cc < 3) { stage(cc + 1, (cc + 1) & 1); CP_WAIT1(); }
        else        { CP_WAIT0(); }
        __syncthreads();
        const int b = cc & 1;
#pragma unroll
        for (int ks = 0; ks < 4; ks++) {
            const int kb = ks * 8;
            uint32_t af[4][4], bf[4][2];
#pragma unroll
            for (int mt = 0; mt < 4; mt++) {
                const int row = wr * 64 + mt * 16 + arow8;
                ldsm4(af[mt], smem_u32(&SA1(b, row, kb + akoff)));
            }
#pragma unroll
            for (int nt = 0; nt < 4; nt++) {
                const uint32_t* p = Bg + (size_t)(bn + nt * 8) * 128
                                       + cc * 32 + kb + bk;
                bf[nt][0] = p[0];
                bf[nt][1] = p[4];
            }
#pragma unroll
            for (int mt = 0; mt < 4; mt++)
#pragma unroll
                for (int nt = 0; nt < 4; nt++)
                    mma_f16(acc[mt][nt], af[mt], bf[nt]);
        }
        __syncthreads();
    }

    __half2* C2 = (__half2*)g_C1h;
#pragma unroll
    for (int mt = 0; mt < 4; mt++) {
        const int row0 = m0 + wr * 64 + mt * 16 + (lane >> 2);
#pragma unroll
        for (int nt = 0; nt < 4; nt++) {
            const int col0 = colOff + wc * 32 + nt * 8 + (lane & 3) * 2;
            C2[(size_t)row0 * 128 + (col0 >> 1)] =
                __floats2half2_rn(fmaxf(acc[mt][nt][0], 0.f),
                                  fmaxf(acc[mt][nt][1], 0.f));
            C2[(size_t)(row0 + 8) * 128 + (col0 >> 1)] =
                __floats2half2_rn(fmaxf(acc[mt][nt][2], 0.f),
                                  fmaxf(acc[mt][nt][3], 0.f));
        }
    }
    GDC_LAUNCH();
}

// ---------------- k_last: mean10(C1) + layer-1 GEMM + norm + dot ---------
#define LA(b, h, r, c) smu[(b) * 10368 + (h) * 576 + (r) * 36 + (c)]
#define LB(b, m, n, c) smu[(b) * 10368 + 1152 + (m) * 4608 + (n) * 36 + (c)]
#define L_SMEM (3 * 10368 * 4)

__global__ void __launch_bounds__(256)
k_last(const float* __restrict__ w_out, const float* __restrict__ b_out,
       float* __restrict__ out) {
    extern __shared__ uint32_t smu[];
    const int tid = threadIdx.x, lane = tid & 31, wid = tid >> 5;
    const int h  = wid >> 2;
    const int cb = (wid & 3) * 32;
    const int m0 = blockIdx.x * LROWS;

    GDC_WAIT();

    const float4* __restrict__ C1f4 = (const float4*)g_C1h;
    const uint4*  __restrict__ C1u4 = (const uint4*)g_C1h;
    const float4* __restrict__ WT4  =
        (const float4*)(g_WTh + 2 * (size_t)WMAT);

    const int arow8 = (lane & 7) + ((lane >> 3) & 1) * 8;
    const int akoff = ((lane >> 4) & 1) * 4;
    const int brow8 = (lane & 7) + ((lane >> 4) & 1) * 8;
    const int bkoff = ((lane >> 3) & 1) * 4;

    float acc[4][4];
#pragma unroll
    for (int nt = 0; nt < 4; nt++)
#pragma unroll
        for (int q = 0; q < 4; q++) acc[nt][q] = 0.f;

    auto stage = [&](int cc, int b) {
#pragma unroll
        for (int u = 0; u < 8; u++) {
            int fid = u * 256 + tid;
            int mat = fid >> 10, rem = fid & 1023;
            int n = rem >> 3, q = rem & 7;
            cp16(smem_u32(&LB(b, mat, n, q * 4)),
                 &WT4[(size_t)mat * 4096 + (size_t)n * 32 + cc * 8 + q]);
        }
        if (tid < 128) {
            int row = tid >> 3, q = tid & 7;
            cp16(smem_u32(&LA(b, 0, row, q * 4)),
                 &C1f4[(size_t)(M1SZ + m0 + row) * 32 + cc * 8 + q]);
        }
        CP_COMMIT();
        if (tid >= 128) {
            int t2 = tid - 128;
            int row = t2 >> 3, q = t2 & 7;
            float f[8];
#pragma unroll
            for (int x = 0; x < 8; x++) f[x] = 0.f;
#pragma unroll
            for (int s = 0; s < NS0; s++) {
                uint4 u = C1u4[(size_t)((m0 + row) * NS0 + s) * 32 + cc * 8 + q];
                const __half2* ph = (const __half2*)&u;
#pragma unroll
                for (int x = 0; x < 4; x++) {
                    float2 v = __half22float2(ph[x]);
                    f[x * 2 + 0] += v.x;
                    f[x * 2 + 1] += v.y;
                }
            }
            const float inv = 1.0f / NS0;
            uint4 o;
            __half2 h0 = __floats2half2_rn(f[0] * inv, f[1] * inv);
            __half2 h1 = __floats2half2_rn(f[2] * inv, f[3] * inv);
            __half2 h2 = __floats2half2_rn(f[4] * inv, f[5] * inv);
            __half2 h3 = __floats2half2_rn(f[6] * inv, f[7] * inv);
            o.x = *(uint32_t*)&h0; o.y = *(uint32_t*)&h1;
            o.z = *(uint32_t*)&h2; o.w = *(uint32_t*)&h3;
            *(uint4*)&LA(b, 1, row, q * 4) = o;
        }
    };

    stage(0, 0);
    stage(1, 1);
    for (int cc = 0; cc < 4; cc++) {
        const int b = cc - (cc / 3) * 3;
        if (cc == 3) { CP_WAIT0(); } else { CP_WAIT1(); }
        __syncthreads();
        if (cc < 2) stage(cc + 2, (cc + 2) - ((cc + 2) / 3) * 3);
#pragma unroll
        for (int ks = 0; ks < 4; ks++) {
            const int kb = ks * 8;
            uint32_t af[4], bf[4][2];
            ldsm4(af, smem_u32(&LA(b, h, arow8, kb + akoff)));
#pragma unroll
            for (int p = 0; p < 2; p++) {
                const int row = cb + p * 16 + brow8;
                uint32_t r[4];
                ldsm4(r, smem_u32(&LB(b, h, row, kb + bkoff)));
                bf[2 * p][0] = r[0]; bf[2 * p][1] = r[1];
                bf[2 * p + 1][0] = r[2]; bf[2 * p + 1][1] = r[3];
            }
#pragma unroll
            for (int nt = 0; nt < 4; nt++)
                mma_f16(acc[nt], af, bf[nt]);
        }
        __syncthreads();
    }

    float* ssm = (float*)smu;
    float* dvm = (float*)smu + 16;
    if (tid < 32) ((float*)smu)[tid] = 0.f;
    __syncthreads();

#pragma unroll
    for (int pair = 0; pair < 2; pair++) {
        const int lr = pair * 8 + (lane >> 2);
        float ss = 0.f, dv = 0.f;
#pragma unroll
        for (int nt = 0; nt < 4; nt++) {
            const int col0 = h * 128 + cb + nt * 8 + (lane & 3) * 2;
            const float h0 = fmaxf(acc[nt][pair * 2 + 0], 0.f);
            const float h1 = fmaxf(acc[nt][pair * 2 + 1], 0.f);
            ss += h0 * h0 + h1 * h1;
            dv += h0 * w_out[col0] + h1 * w_out[col0 + 1];
        }
        ss += __shfl_xor_sync(0xffffffffu, ss, 1);
        ss += __shfl_xor_sync(0xffffffffu, ss, 2);
        dv += __shfl_xor_sync(0xffffffffu, dv, 1);
        dv += __shfl_xor_sync(0xffffffffu, dv, 2);
        if ((lane & 3) == 0) {
            atomicAdd(&ssm[lr], ss);
            atomicAdd(&dvm[lr], dv);
        }
    }
    __syncthreads();
    if (tid < LROWS)
        out[m0 + tid] = dvm[tid] / sqrtf(fmaxf(ssm[tid], 1e-12f)) + b_out[0];
}

// ---------------- launch ----------------
extern "C" void kernel_launch(void* const* d_in, const int* in_sizes, int n_in,
                              void* d_out, int out_size) {
    const float* feat     = (const float*)d_in[0];
    const float* ws0      = (const float*)d_in[1];
    const float* wn0      = (const float*)d_in[2];
    const float* ws1      = (const float*)d_in[3];
    const float* wn1      = (const float*)d_in[4];
    const float* wout     = (const float*)d_in[5];
    const float* bout     = (const float*)d_in[6];
    const int*   node_ids = (const int*)d_in[7];
    const int*   adj      = (const int*)d_in[8];
    float* out = (float*)d_out;
    (void)in_sizes; (void)n_in; (void)out_size;

    uint32_t f0a, f0b, f1a, f1b, l0a, l0b, l1a, l1b;
    tf2x32(0u, 42u, 0u, 0u, f0a, f0b);
    tf2x32(0u, 42u, 0u, 1u, f1a, f1b);
    tf2x32(f0a, f0b, 0u, 1u, l0a, l0b);
    tf2x32(f1a, f1b, 0u, 1u, l1a, l1b);

    cudaFuncSetAttribute(k_gemm1,
                         cudaFuncAttributeMaxDynamicSharedMemorySize, G1_SMEM);
    cudaFuncSetAttribute(k_last,
                         cudaFuncAttributeMaxDynamicSharedMemorySize, L_SMEM);

    k_prep<<<HOP1_BLKS + WT_BLKS + HOP0_BLKS, 256>>>(
        (const float4*)feat, adj, node_ids, ws0, wn0, ws1, wn1,
        l0a, l0b, l1a, l1b);

    cudaLaunchAttribute pdl[1];
    pdl[0].id = cudaLaunchAttributeProgrammaticStreamSerialization;
    pdl[0].val.programmaticStreamSerializationAllowed = 1;

    cudaLaunchConfig_t cfg1 = {};
    cfg1.gridDim = dim3(MEXT / BM, 2);
    cfg1.blockDim = dim3(256);
    cfg1.dynamicSmemBytes = G1_SMEM;
    cfg1.stream = 0;
    cfg1.attrs = pdl;
    cfg1.numAttrs = 1;
    cudaLaunchKernelEx(&cfg1, k_gemm1);

    cudaLaunchConfig_t cfg2 = {};
    cfg2.gridDim = dim3(BATCH / LROWS);
    cfg2.blockDim = dim3(256);
    cfg2.dynamicSmemBytes = L_SMEM;
    cfg2.stream = 0;
    cfg2.attrs = pdl;
    cfg2.numAttrs = 1;
    cudaLaunchKernelEx(&cfg2, k_last, wout, bout, out);
}

// round 17
// speedup vs baseline: 1.1223x; 1.1223x over previous
#include <cuda_runtime.h>
#include <cuda_fp16.h>
#include <stdint.h>
#include <math.h>

#define FEAT     256
#define MAX_DEG  128
#define BATCH    1024
#define NS0      10
#define NS1      25
#define M1SZ     (BATCH * NS0)     /* 10240 */
#define MEXT     (M1SZ + BATCH)    /* 11264 */
#define BM       128               /* gemm1 M-tile */
#define HOP1_BLKS (M1SZ / 4)       /* 2560 */
#define WT_BLKS   128
#define HOP0_BLKS (BATCH / 4)      /* 256 */
#define WMAT     (128 * FEAT)      /* halves per K-major weight matrix */
#define LROWS    16

// ---------------- scratch (fp16) ----------------
__device__ __align__(16) __half g_H1h[MEXT * FEAT];
__device__ __align__(16) __half g_M1h[MEXT * FEAT];
__device__ __align__(16) __half g_C1h[MEXT * FEAT];   // rows M1SZ.. are C0
__device__ __align__(16) __half g_WTh[4 * WMAT];

// ---------------- threefry2x32 ----------------
__host__ __device__ __forceinline__ uint32_t rotl32_(uint32_t x, int r) {
    return (x << r) | (x >> (32 - r));
}
__host__ __device__ inline void tf2x32(uint32_t k0, uint32_t k1,
                                       uint32_t x0, uint32_t x1,
                                       uint32_t &o0, uint32_t &o1) {
    uint32_t ks2 = k0 ^ k1 ^ 0x1BD11BDAu;
    x0 += k0; x1 += k1;
#define TFR(r) { x0 += x1; x1 = rotl32_(x1, (r)); x1 ^= x0; }
    TFR(13) TFR(15) TFR(26) TFR(6)
    x0 += k1;  x1 += ks2 + 1u;
    TFR(17) TFR(29) TFR(16) TFR(24)
    x0 += ks2; x1 += k0 + 2u;
    TFR(13) TFR(15) TFR(26) TFR(6)
    x0 += k0;  x1 += k1 + 3u;
    TFR(17) TFR(29) TFR(16) TFR(24)
    x0 += k1;  x1 += ks2 + 4u;
    TFR(13) TFR(15) TFR(26) TFR(6)
    x0 += ks2; x1 += k0 + 5u;
#undef TFR
    o0 = x0; o1 = x1;
}
__device__ __forceinline__ int rnd_col(uint32_t k0, uint32_t k1, uint32_t t) {
    uint32_t a, b;
    tf2x32(k0, k1, 0u, t, a, b);
    return (int)((a ^ b) & (uint32_t)(MAX_DEG - 1));
}

// ---------------- helpers ----------------
__device__ __forceinline__ void mma_f16(float c[4], const uint32_t a[4],
                                        const uint32_t b[2]) {
    asm volatile(
        "mma.sync.aligned.m16n8k16.row.col.f32.f16.f16.f32 "
        "{%0,%1,%2,%3}, {%4,%5,%6,%7}, {%8,%9}, {%0,%1,%2,%3};"
        : "+f"(c[0]), "+f"(c[1]), "+f"(c[2]), "+f"(c[3])
        : "r"(a[0]), "r"(a[1]), "r"(a[2]), "r"(a[3]), "r"(b[0]), "r"(b[1]));
}
__device__ __forceinline__ void ldsm4(uint32_t r[4], uint32_t addr) {
    asm volatile(
        "ldmatrix.sync.aligned.m8n8.x4.shared.b16 {%0,%1,%2,%3}, [%4];"
        : "=r"(r[0]), "=r"(r[1]), "=r"(r[2]), "=r"(r[3]) : "r"(addr));
}
__device__ __forceinline__ uint32_t smem_u32(const void* p) {
    return (uint32_t)__cvta_generic_to_shared(p);
}
__device__ __forceinline__ void cp16(uint32_t s, const void* g) {
    asm volatile("cp.async.cg.shared.global [%0], [%1], 16;" :: "r"(s), "l"(g));
}
#define CP_COMMIT() asm volatile("cp.async.commit_group;" ::: "memory")
#define CP_WAIT1()  asm volatile("cp.async.wait_group 1;" ::: "memory")
#define CP_WAIT0()  asm volatile("cp.async.wait_group 0;" ::: "memory")
#define GDC_WAIT()  asm volatile("griddepcontrol.wait;" ::: "memory")
#define GDC_LAUNCH() asm volatile("griddepcontrol.launch_dependents;" ::: "memory")

__device__ __forceinline__ void st_half4(void* dst, float4 v) {
    __half2 a = __floats2half2_rn(v.x, v.y);
    __half2 b = __floats2half2_rn(v.z, v.w);
    uint2 u;
    u.x = *(uint32_t*)&a;
    u.y = *(uint32_t*)&b;
    *(uint2*)dst = u;
}

// ---------------- prep: hop1 + weight transposes + hop0 (proven R12) ------
__global__ void __launch_bounds__(256)
k_prep(const float4* __restrict__ feat4, const int* __restrict__ adj,
       const int* __restrict__ node_ids,
       const float* __restrict__ w0, const float* __restrict__ w1,
       const float* __restrict__ w2, const float* __restrict__ w3,
       uint32_t l0a, uint32_t l0b, uint32_t l1a, uint32_t l1b) {
    const int tid = threadIdx.x;
    uint2* H1u = (uint2*)g_H1h;
    uint2* M1u = (uint2*)g_M1h;

    if (blockIdx.x >= HOP1_BLKS + WT_BLKS) {
        __shared__ int s1g[40];
        const int i0 = (blockIdx.x - HOP1_BLKS - WT_BLKS) * 4;
        if (tid < 40) {
            const int j = i0 * NS0 + tid;
            int c0 = rnd_col(l0a, l0b, (uint32_t)j);
            s1g[tid] = adj[node_ids[j / NS0] * MAX_DEG + c0];
        }
        __syncthreads();
        const int lj = tid >> 6, c = tid & 63;
        const int i = i0 + lj;
        st_half4(&H1u[(size_t)(M1SZ + i) * 64 + c],
                 feat4[(size_t)node_ids[i] * 64 + c]);
        float ax = 0.f, ay = 0.f, az = 0.f, aw = 0.f;
#pragma unroll
        for (int s = 0; s < NS0; s++) {
            float4 v = feat4[(size_t)s1g[lj * NS0 + s] * 64 + c];
            ax += v.x; ay += v.y; az += v.z; aw += v.w;
        }
        const float inv = 1.0f / NS0;
        st_half4(&M1u[(size_t)(M1SZ + i) * 64 + c],
                 make_float4(ax * inv, ay * inv, az * inv, aw * inv));
        GDC_LAUNCH();
        return;
    }
    if (blockIdx.x >= HOP1_BLKS) {
        __shared__ float tile[32][33];
        const int wb = blockIdx.x - HOP1_BLKS;
        const int mat = wb >> 5;
        const int sub = wb & 31;
        const float* W = (mat == 0) ? w0 : (mat == 1) ? w1 : (mat == 2) ? w2 : w3;
        __half* WT = g_WTh + mat * WMAT;
        const int k0 = (sub >> 2) * 32;
        const int n0 = (sub & 3) * 32;
        const int c = tid & 31, rw = tid >> 5;
#pragma unroll
        for (int r = rw; r < 32; r += 8)
            tile[r][c] = W[(k0 + r) * 128 + n0 + c];
        __syncthreads();
#pragma unroll
        for (int r = rw; r < 32; r += 8)
            WT[(n0 + r) * FEAT + k0 + c] = __float2half_rn(tile[c][r]);
        GDC_LAUNCH();
        return;
    }
    const int j0 = blockIdx.x * 4;
    __shared__ int s1sh[4];
    __shared__ int s2s[4][NS1];
    if (tid < 4) {
        int j = j0 + tid;
        int c0 = rnd_col(l0a, l0b, (uint32_t)j);
        s1sh[tid] = adj[node_ids[j / NS0] * MAX_DEG + c0];
    }
    __syncthreads();
    if (tid < 4 * NS1) {
        int lj = tid / NS1, s = tid - lj * NS1;
        int c1 = rnd_col(l1a, l1b, (uint32_t)((j0 + lj) * NS1 + s));
        s2s[lj][s] = adj[s1sh[lj] * MAX_DEG + c1];
    }
    __syncthreads();
    const int lj = tid >> 6, c = tid & 63;
    const int j = j0 + lj;
    st_half4(&H1u[(size_t)j * 64 + c], feat4[(size_t)s1sh[lj] * 64 + c]);
    float ax = 0.f, ay = 0.f, az = 0.f, aw = 0.f;
#pragma unroll
    for (int s = 0; s < NS1; s++) {
        float4 v = feat4[(size_t)s2s[lj][s] * 64 + c];
        ax += v.x; ay += v.y; az += v.z; aw += v.w;
    }
    const float inv = 1.0f / NS1;
    st_half4(&M1u[(size_t)j * 64 + c],
             make_float4(ax * inv, ay * inv, az * inv, aw * inv));
    GDC_LAUNCH();
}

// ---------------- gemm1: fp16 mma, BM=128, 2-stage, ldmatrix (R15) -------
#define SA1(b, r, c) smu[(b) * 9216 + (r) * 36 + (c)]
#define SB1(b, r, c) smu[(b) * 9216 + 4608 + (r) * 36 + (c)]
#define G1_SMEM (2 * 9216 * 4)

__global__ void __launch_bounds__(256)
k_gemm1() {
    extern __shared__ uint32_t smu[];
    const int tid = threadIdx.x, lane = tid & 31, wid = tid >> 5;
    const int wr = wid & 1, wc = wid >> 1;
    const int m0 = blockIdx.x * BM;

    GDC_WAIT();

    const float4* __restrict__ A4 =
        (const float4*)(blockIdx.y ? g_M1h : g_H1h);
    const float4* __restrict__ B4 =
        (const float4*)(g_WTh + (size_t)blockIdx.y * WMAT);
    const int colOff = blockIdx.y * 128;

    const int arow8 = (lane & 7) + ((lane >> 3) & 1) * 8;
    const int akoff = ((lane >> 4) & 1) * 4;
    const int brow8 = (lane & 7) + ((lane >> 4) & 1) * 8;
    const int bkoff = ((lane >> 3) & 1) * 4;

    float acc[4][4][4];
#pragma unroll
    for (int mt = 0; mt < 4; mt++)
#pragma unroll
        for (int nt = 0; nt < 4; nt++)
#pragma unroll
            for (int q = 0; q < 4; q++) acc[mt][nt][q] = 0.f;

    auto stage = [&](int cc, int b) {
#pragma unroll
        for (int u = 0; u < 4; u++) {
            int fid = u * 256 + tid;
            int row = fid >> 3, q = fid & 7;
            cp16(smem_u32(&SA1(b, row, q * 4)),
                 &A4[(size_t)(m0 + row) * 32 + cc * 8 + q]);
        }
#pragma unroll
        for (int u = 0; u < 4; u++) {
            int fid = u * 256 + tid;
            int row = fid >> 3, q = fid & 7;
            cp16(smem_u32(&SB1(b, row, q * 4)),
                 &B4[(size_t)row * 32 + cc * 8 + q]);
        }
        CP_COMMIT();
    };

    stage(0, 0);
    for (int cc = 0; cc < 4; cc++) {
        if (cc < 3) { stage(cc + 1, (cc + 1) & 1); CP_WAIT1(); }
        else        { CP_WAIT0(); }
        __syncthreads();
        const int b = cc & 1;
#pragma unroll
        for (int ks = 0; ks < 4; ks++) {
            const int kb = ks * 8;
            uint32_t af[4][4], bf[4][2];
#pragma unroll
            for (int mt = 0; mt < 4; mt++) {
                const int row = wr * 64 + mt * 16 + arow8;
                ldsm4(af[mt], smem_u32(&SA1(b, row, kb + akoff)));
            }
#pragma unroll
            for (int p = 0; p < 2; p++) {
                const int row = wc * 32 + p * 16 + brow8;
                uint32_t r[4];
                ldsm4(r, smem_u32(&SB1(b, row, kb + bkoff)));
                bf[2 * p][0] = r[0]; bf[2 * p][1] = r[1];
                bf[2 * p + 1][0] = r[2]; bf[2 * p + 1][1] = r[3];
            }
#pragma unroll
            for (int mt = 0; mt < 4; mt++)
#pragma unroll
                for (int nt = 0; nt < 4; nt++)
                    mma_f16(acc[mt][nt], af[mt], bf[nt]);
        }
        __syncthreads();
    }

    __half2* C2 = (__half2*)g_C1h;
#pragma unroll
    for (int mt = 0; mt < 4; mt++) {
        const int row0 = m0 + wr * 64 + mt * 16 + (lane >> 2);
#pragma unroll
        for (int nt = 0; nt < 4; nt++) {
            const int col0 = colOff + wc * 32 + nt * 8 + (lane & 3) * 2;
            C2[(size_t)row0 * 128 + (col0 >> 1)] =
                __floats2half2_rn(fmaxf(acc[mt][nt][0], 0.f),
                                  fmaxf(acc[mt][nt][1], 0.f));
            C2[(size_t)(row0 + 8) * 128 + (col0 >> 1)] =
                __floats2half2_rn(fmaxf(acc[mt][nt][2], 0.f),
                                  fmaxf(acc[mt][nt][3], 0.f));
        }
    }
    GDC_LAUNCH();
}

// ---------------- k_last: mean10(C1) + layer-1 GEMM + norm + dot (R15) ---
#define LA(b, h, r, c) smu[(b) * 10368 + (h) * 576 + (r) * 36 + (c)]
#define LB(b, m, n, c) smu[(b) * 10368 + 1152 + (m) * 4608 + (n) * 36 + (c)]
#define L_SMEM (3 * 10368 * 4)

__global__ void __launch_bounds__(256)
k_last(const float* __restrict__ w_out, const float* __restrict__ b_out,
       float* __restrict__ out) {
    extern __shared__ uint32_t smu[];
    const int tid = threadIdx.x, lane = tid & 31, wid = tid >> 5;
    const int h  = wid >> 2;
    const int cb = (wid & 3) * 32;
    const int m0 = blockIdx.x * LROWS;

    GDC_WAIT();

    const float4* __restrict__ C1f4 = (const float4*)g_C1h;
    const uint4*  __restrict__ C1u4 = (const uint4*)g_C1h;
    const float4* __restrict__ WT4  =
        (const float4*)(g_WTh + 2 * (size_t)WMAT);

    const int arow8 = (lane & 7) + ((lane >> 3) & 1) * 8;
    const int akoff = ((lane >> 4) & 1) * 4;
    const int brow8 = (lane & 7) + ((lane >> 4) & 1) * 8;
    const int bkoff = ((lane >> 3) & 1) * 4;

    float acc[4][4];
#pragma unroll
    for (int nt = 0; nt < 4; nt++)
#pragma unroll
        for (int q = 0; q < 4; q++) acc[nt][q] = 0.f;

    auto stage = [&](int cc, int b) {
#pragma unroll
        for (int u = 0; u < 8; u++) {
            int fid = u * 256 + tid;
            int mat = fid >> 10, rem = fid & 1023;
            int n = rem >> 3, q = rem & 7;
            cp16(smem_u32(&LB(b, mat, n, q * 4)),
                 &WT4[(size_t)mat * 4096 + (size_t)n * 32 + cc * 8 + q]);
        }
        if (tid < 128) {
            int row = tid >> 3, q = tid & 7;
            cp16(smem_u32(&LA(b, 0, row, q * 4)),
                 &C1f4[(size_t)(M1SZ + m0 + row) * 32 + cc * 8 + q]);
        }
        CP_COMMIT();
        if (tid >= 128) {
            int t2 = tid - 128;
            int row = t2 >> 3, q = t2 & 7;
            float f[8];
#pragma unroll
            for (int x = 0; x < 8; x++) f[x] = 0.f;
#pragma unroll
            for (int s = 0; s < NS0; s++) {
                uint4 u = C1u4[(size_t)((m0 + row) * NS0 + s) * 32 + cc * 8 + q];
                const __half2* ph = (const __half2*)&u;
#pragma unroll
                for (int x = 0; x < 4; x++) {
                    float2 v = __half22float2(ph[x]);
                    f[x * 2 + 0] += v.x;
                    f[x * 2 + 1] += v.y;
                }
            }
            const float inv = 1.0f / NS0;
            uint4 o;
            __half2 h0 = __floats2half2_rn(f[0] * inv, f[1] * inv);
            __half2 h1 = __floats2half2_rn(f[2] * inv, f[3] * inv);
            __half2 h2 = __floats2half2_rn(f[4] * inv, f[5] * inv);
            __half2 h3 = __floats2half2_rn(f[6] * inv, f[7] * inv);
            o.x = *(uint32_t*)&h0; o.y = *(uint32_t*)&h1;
            o.z = *(uint32_t*)&h2; o.w = *(uint32_t*)&h3;
            *(uint4*)&LA(b, 1, row, q * 4) = o;
        }
    };

    stage(0, 0);
    stage(1, 1);
    for (int cc = 0; cc < 4; cc++) {
        const int b = cc - (cc / 3) * 3;
        if (cc == 3) { CP_WAIT0(); } else { CP_WAIT1(); }
        __syncthreads();
        if (cc < 2) stage(cc + 2, (cc + 2) - ((cc + 2) / 3) * 3);
#pragma unroll
        for (int ks = 0; ks < 4; ks++) {
            const int kb = ks * 8;
            uint32_t af[4], bf[4][2];
            ldsm4(af, smem_u32(&LA(b, h, arow8, kb + akoff)));
#pragma unroll
            for (int p = 0; p < 2; p++) {
                const int row = cb + p * 16 + brow8;
                uint32_t r[4];
                ldsm4(r, smem_u32(&LB(b, h, row, kb + bkoff)));
                bf[2 * p][0] = r[0]; bf[2 * p][1] = r[1];
                bf[2 * p + 1][0] = r[2]; bf[2 * p + 1][1] = r[3];
            }
#pragma unroll
            for (int nt = 0; nt < 4; nt++)
                mma_f16(acc[nt], af, bf[nt]);
        }
        __syncthreads();
    }

    float* ssm = (float*)smu;
    float* dvm = (float*)smu + 16;
    if (tid < 32) ((float*)smu)[tid] = 0.f;
    __syncthreads();

#pragma unroll
    for (int pair = 0; pair < 2; pair++) {
        const int lr = pair * 8 + (lane >> 2);
        float ss = 0.f, dv = 0.f;
#pragma unroll
        for (int nt = 0; nt < 4; nt++) {
            const int col0 = h * 128 + cb + nt * 8 + (lane & 3) * 2;
            const float h0 = fmaxf(acc[nt][pair * 2 + 0], 0.f);
            const float h1 = fmaxf(acc[nt][pair * 2 + 1], 0.f);
            ss += h0 * h0 + h1 * h1;
            dv += h0 * w_out[col0] + h1 * w_out[col0 + 1];
        }
        ss += __shfl_xor_sync(0xffffffffu, ss, 1);
        ss += __shfl_xor_sync(0xffffffffu, ss, 2);
        dv += __shfl_xor_sync(0xffffffffu, dv, 1);
        dv += __shfl_xor_sync(0xffffffffu, dv, 2);
        if ((lane & 3) == 0) {
            atomicAdd(&ssm[lr], ss);
            atomicAdd(&dvm[lr], dv);
        }
    }
    __syncthreads();
    if (tid < LROWS)
        out[m0 + tid] = dvm[tid] / sqrtf(fmaxf(ssm[tid], 1e-12f)) + b_out[0];
}

// ---------------- launch ----------------
extern "C" void kernel_launch(void* const* d_in, const int* in_sizes, int n_in,
                              void* d_out, int out_size) {
    const float* feat     = (const float*)d_in[0];
    const float* ws0      = (const float*)d_in[1];
    const float* wn0      = (const float*)d_in[2];
    const float* ws1      = (const float*)d_in[3];
    const float* wn1      = (const float*)d_in[4];
    const float* wout     = (const float*)d_in[5];
    const float* bout     = (const float*)d_in[6];
    const int*   node_ids = (const int*)d_in[7];
    const int*   adj      = (const int*)d_in[8];
    float* out = (float*)d_out;
    (void)in_sizes; (void)n_in; (void)out_size;

    uint32_t f0a, f0b, f1a, f1b, l0a, l0b, l1a, l1b;
    tf2x32(0u, 42u, 0u, 0u, f0a, f0b);
    tf2x32(0u, 42u, 0u, 1u, f1a, f1b);
    tf2x32(f0a, f0b, 0u, 1u, l0a, l0b);
    tf2x32(f1a, f1b, 0u, 1u, l1a, l1b);

    cudaFuncSetAttribute(k_gemm1,
                         cudaFuncAttributeMaxDynamicSharedMemorySize, G1_SMEM);
    cudaFuncSetAttribute(k_last,
                         cudaFuncAttributeMaxDynamicSharedMemorySize, L_SMEM);

    k_prep<<<HOP1_BLKS + WT_BLKS + HOP0_BLKS, 256>>>(
        (const float4*)feat, adj, node_ids, ws0, wn0, ws1, wn1,
        l0a, l0b, l1a, l1b);

    cudaLaunchAttribute pdl[1];
    pdl[0].id = cudaLaunchAttributeProgrammaticStreamSerialization;
    pdl[0].val.programmaticStreamSerializationAllowed = 1;

    cudaLaunchConfig_t cfg1 = {};
    cfg1.gridDim = dim3(MEXT / BM, 2);
    cfg1.blockDim = dim3(256);
    cfg1.dynamicSmemBytes = G1_SMEM;
    cfg1.stream = 0;
    cfg1.attrs = pdl;
    cfg1.numAttrs = 1;
    cudaLaunchKernelEx(&cfg1, k_gemm1);

    cudaLaunchConfig_t cfg2 = {};
    cfg2.gridDim = dim3(BATCH / LROWS);
    cfg2.blockDim = dim3(256);
    cfg2.dynamicSmemBytes = L_SMEM;
    cfg2.stream = 0;
    cfg2.attrs = pdl;
    cfg2.numAttrs = 1;
    cudaLaunchKernelEx(&cfg2, k_last, wout, bout, out);
}